// round 5
// baseline (speedup 1.0000x reference)
#include <cuda_runtime.h>

// GNN_70145405878616 — persistent grid-stride, 8 lanes/node, prefetched.
// out[b,o] = tanh(tanh( bc[o] + sum_c Wc[o,c,0]*h[b,c] + Wc[o,c,1]*p[b,c] ))
//   h[b,c] = tanh( bs[c] + sum_j Ws[c,j]*x[b,j] ),  p[b,c] = mean_k nb[b,c,k]
//
// HBM-bound (792 MB). 8-lane groups read fully aligned 128B lines (768B/node).
// Persistent CTAs + explicit next-node register prefetch keep 6 independent
// LDG.128 in flight per thread across iterations, hiding the epilogue.

__device__ __forceinline__ float htanh(float x) {
    float y;
    asm("tanh.approx.f32 %0, %1;" : "=f"(y) : "f"(x));
    return y;
}

__global__ __launch_bounds__(256) void gnn_kernel(
        const float* __restrict__ x,
        const float* __restrict__ nb,
        const float* __restrict__ Ws,
        const float* __restrict__ bs,
        const float* __restrict__ Wc,
        const float* __restrict__ bc,
        float* __restrict__ out,
        int B) {
    const int lane    = threadIdx.x & 7;
    const int group   = (blockIdx.x * blockDim.x + threadIdx.x) >> 3;
    const int ngroups = (gridDim.x * blockDim.x) >> 3;
    const unsigned gm = 0xFFu << (threadIdx.x & 24);

    const float4* __restrict__ nb4 = reinterpret_cast<const float4*>(nb);

    int node = group;
    if (node >= B) return;

    // Load current node
    const float4* base = nb4 + (size_t)node * 48;
    float4 a0 = base[lane],      b0 = base[lane + 8];
    float4 a1 = base[lane + 16], b1 = base[lane + 24];
    float4 a2 = base[lane + 32], b2 = base[lane + 40];

    while (true) {
        const int nn = node + ngroups;
        // Prefetch next node into separate registers (overlaps epilogue).
        float4 na0, nb0, na1, nb1, na2, nb2;
        if (nn < B) {
            const float4* nbase = nb4 + (size_t)nn * 48;
            na0 = nbase[lane];      nb0 = nbase[lane + 8];
            na1 = nbase[lane + 16]; nb1 = nbase[lane + 24];
            na2 = nbase[lane + 32]; nb2 = nbase[lane + 40];
        }

        float s0 = ((a0.x + b0.x) + (a0.y + b0.y)) + ((a0.z + b0.z) + (a0.w + b0.w));
        float s1 = ((a1.x + b1.x) + (a1.y + b1.y)) + ((a1.z + b1.z) + (a1.w + b1.w));
        float s2 = ((a2.x + b2.x) + (a2.y + b2.y)) + ((a2.z + b2.z) + (a2.w + b2.w));

        #pragma unroll
        for (int off = 4; off > 0; off >>= 1) {
            s0 += __shfl_xor_sync(gm, s0, off);
            s1 += __shfl_xor_sync(gm, s1, off);
            s2 += __shfl_xor_sync(gm, s2, off);
        }

        if (lane == 0) {
            const float inv = 1.0f / 64.0f;
            float p[3] = { s0 * inv, s1 * inv, s2 * inv };

            const float* __restrict__ xp = x + (size_t)node * 3;
            const float x0 = xp[0], x1 = xp[1], x2 = xp[2];

            float h[3];
            #pragma unroll
            for (int o = 0; o < 3; ++o) {
                h[o] = htanh(fmaf(Ws[o * 3 + 0], x0,
                             fmaf(Ws[o * 3 + 1], x1,
                             fmaf(Ws[o * 3 + 2], x2, bs[o]))));
            }

            float* __restrict__ op = out + (size_t)node * 3;
            #pragma unroll
            for (int o = 0; o < 3; ++o) {
                float z = bc[o];
                #pragma unroll
                for (int c = 0; c < 3; ++c) {
                    z = fmaf(Wc[o * 6 + c * 2 + 0], h[c], z);
                    z = fmaf(Wc[o * 6 + c * 2 + 1], p[c], z);
                }
                op[o] = htanh(htanh(z));
            }
        }

        if (nn >= B) break;
        node = nn;
        a0 = na0; b0 = nb0;
        a1 = na1; b1 = nb1;
        a2 = na2; b2 = nb2;
    }
}

extern "C" void kernel_launch(void* const* d_in, const int* in_sizes, int n_in,
                              void* d_out, int out_size) {
    const float* x  = (const float*)d_in[0];   // [B,3,1]
    const float* nb = (const float*)d_in[1];   // [B,3,64]
    const float* Ws = (const float*)d_in[2];   // [3,3]
    const float* bs = (const float*)d_in[3];   // [3]
    const float* Wc = (const float*)d_in[4];   // [3,3,2]
    const float* bc = (const float*)d_in[5];   // [3]
    float* out = (float*)d_out;                // [B,3,1]

    const int B = in_sizes[0] / 3;
    const int threads = 256;                   // 32 groups per block
    // Persistent-ish: ~8 CTAs/SM target on 148 SMs (extra waves are cheap).
    int blocks = 148 * 8;
    const long long total_groups = (long long)B;   // one group per node needed at most
    const long long max_blocks = (total_groups * 8 + threads - 1) / threads;
    if (blocks > max_blocks) blocks = (int)max_blocks;

    gnn_kernel<<<blocks, threads>>>(x, nb, Ws, bs, Wc, bc, out, B);
}

// round 6
// speedup vs baseline: 1.0561x; 1.0561x over previous
#include <cuda_runtime.h>

// GNN_70145405878616 — 8 lanes per node, coalesced 128B lines, streaming hints.
// out[b,o] = tanh(tanh( bc[o] + sum_c Wc[o,c,0]*h[b,c] + Wc[o,c,1]*p[b,c] ))
//   h[b,c] = tanh( bs[c] + sum_j Ws[c,j]*x[b,j] ),  p[b,c] = mean_k nb[b,c,k]
//
// HBM-bound: 792 MB mandatory traffic. R4 shape (short CTAs, occ ~90%) was
// the best measured; this adds evict-first (__ldcs/__stcs) on the read-once
// neighbor stream and write-once output to keep L2 in pass-through mode.

__device__ __forceinline__ float htanh(float x) {
    float y;
    asm("tanh.approx.f32 %0, %1;" : "=f"(y) : "f"(x));
    return y;
}

__global__ __launch_bounds__(256) void gnn_kernel(
        const float* __restrict__ x,
        const float* __restrict__ nb,
        const float* __restrict__ Ws,
        const float* __restrict__ bs,
        const float* __restrict__ Wc,
        const float* __restrict__ bc,
        float* __restrict__ out,
        int B) {
    const int gtid = blockIdx.x * blockDim.x + threadIdx.x;
    const int node = gtid >> 3;        // 8 lanes per node
    const int lane = gtid & 7;
    if (node >= B) return;

    const float4* __restrict__ base =
        reinterpret_cast<const float4*>(nb) + (size_t)node * 48;

    // Channel c occupies float4s [c*16, c*16+16). Lane l takes l and l+8.
    // Evict-first: this stream is read exactly once.
    float4 a0 = __ldcs(base + lane),      b0 = __ldcs(base + lane + 8);
    float4 a1 = __ldcs(base + lane + 16), b1 = __ldcs(base + lane + 24);
    float4 a2 = __ldcs(base + lane + 32), b2 = __ldcs(base + lane + 40);

    float s0 = ((a0.x + b0.x) + (a0.y + b0.y)) + ((a0.z + b0.z) + (a0.w + b0.w));
    float s1 = ((a1.x + b1.x) + (a1.y + b1.y)) + ((a1.z + b1.z) + (a1.w + b1.w));
    float s2 = ((a2.x + b2.x) + (a2.y + b2.y)) + ((a2.z + b2.z) + (a2.w + b2.w));

    // Reduce across the 8-lane group (xor offsets 4,2,1 stay in-group).
    const unsigned gm = 0xFFu << (threadIdx.x & 24);
    #pragma unroll
    for (int off = 4; off > 0; off >>= 1) {
        s0 += __shfl_xor_sync(gm, s0, off);
        s1 += __shfl_xor_sync(gm, s1, off);
        s2 += __shfl_xor_sync(gm, s2, off);
    }

    if (lane == 0) {
        const float inv = 1.0f / 64.0f;
        float p[3] = { s0 * inv, s1 * inv, s2 * inv };

        const float* __restrict__ xp = x + (size_t)node * 3;
        const float x0 = __ldg(xp + 0), x1 = __ldg(xp + 1), x2 = __ldg(xp + 2);

        float h[3];
        #pragma unroll
        for (int o = 0; o < 3; ++o) {
            h[o] = htanh(fmaf(__ldg(Ws + o * 3 + 0), x0,
                         fmaf(__ldg(Ws + o * 3 + 1), x1,
                         fmaf(__ldg(Ws + o * 3 + 2), x2, __ldg(bs + o)))));
        }

        float* __restrict__ op = out + (size_t)node * 3;
        #pragma unroll
        for (int o = 0; o < 3; ++o) {
            float z = __ldg(bc + o);
            #pragma unroll
            for (int c = 0; c < 3; ++c) {
                z = fmaf(__ldg(Wc + o * 6 + c * 2 + 0), h[c], z);
                z = fmaf(__ldg(Wc + o * 6 + c * 2 + 1), p[c], z);
            }
            __stcs(op + o, htanh(htanh(z)));
        }
    }
}

extern "C" void kernel_launch(void* const* d_in, const int* in_sizes, int n_in,
                              void* d_out, int out_size) {
    const float* x  = (const float*)d_in[0];   // [B,3,1]
    const float* nb = (const float*)d_in[1];   // [B,3,64]
    const float* Ws = (const float*)d_in[2];   // [3,3]
    const float* bs = (const float*)d_in[3];   // [3]
    const float* Wc = (const float*)d_in[4];   // [3,3,2]
    const float* bc = (const float*)d_in[5];   // [3]
    float* out = (float*)d_out;                // [B,3,1]

    const int B = in_sizes[0] / 3;
    const int threads = 256;                   // 32 nodes per block
    const long long total = (long long)B * 8;
    const int blocks = (int)((total + threads - 1) / threads);

    gnn_kernel<<<blocks, threads>>>(x, nb, Ws, bs, Wc, bc, out, B);
}